// round 1
// baseline (speedup 1.0000x reference)
#include <cuda_runtime.h>
#include <math.h>

#define TT 4096
#define DD 896

constexpr int BM = 128, BN = 128, BK = 16;
constexpr int NBLK  = TT / BM;                 // 32
constexpr int NPAIR = NBLK * (NBLK + 1) / 2;   // 528 causal block pairs

// ---------------- scratch (device globals: allocation-free) ----------------
__device__ float g_h[(size_t)TT * DD];      // normalized hidden states
__device__ float g_g[(size_t)TT * DD];      // anchor g(t)
__device__ float g_sim[(size_t)TT * TT];    // sim -> alpha (in place)
__device__ float g_hn2[TT];                 // ||h_s||^2 (≈1, kept for fidelity)
__device__ float g_maxQ[TT];                // max_{s<=t} (hn2[s] - 2*cross[t,s])

// ---------------- helpers ----------------
__device__ __forceinline__ float blockReduceSum(float v, float* sh) {
    int lane = threadIdx.x & 31, w = threadIdx.x >> 5;
#pragma unroll
    for (int o = 16; o; o >>= 1) v += __shfl_xor_sync(0xffffffffu, v, o);
    __syncthreads();
    if (lane == 0) sh[w] = v;
    __syncthreads();
    if (threadIdx.x == 0) {
        float s = 0.f;
        int nw = (blockDim.x + 31) >> 5;
        for (int i = 0; i < nw; i++) s += sh[i];
        sh[0] = s;
    }
    __syncthreads();
    return sh[0];
}

__device__ __forceinline__ float blockReduceMax(float v, float* sh) {
    int lane = threadIdx.x & 31, w = threadIdx.x >> 5;
#pragma unroll
    for (int o = 16; o; o >>= 1) v = fmaxf(v, __shfl_xor_sync(0xffffffffu, v, o));
    __syncthreads();
    if (lane == 0) sh[w] = v;
    __syncthreads();
    if (threadIdx.x == 0) {
        float m = -3.0e38f;
        int nw = (blockDim.x + 31) >> 5;
        for (int i = 0; i < nw; i++) m = fmaxf(m, sh[i]);
        sh[0] = m;
    }
    __syncthreads();
    return sh[0];
}

__device__ __forceinline__ void atomicMaxF(float* addr, float val) {
    int old = __float_as_int(*addr);
    while (__int_as_float(old) < val) {
        int assumed = old;
        old = atomicCAS((int*)addr, assumed, __float_as_int(val));
        if (old == assumed) break;
    }
}

// decode linear pair index -> (ib >= jb)
__device__ __forceinline__ void triDecode(int b, int& ib, int& jb) {
    int i = (int)floorf((sqrtf(8.0f * (float)b + 1.0f) - 1.0f) * 0.5f);
    while ((i + 1) * (i + 2) / 2 <= b) i++;
    while (i * (i + 1) / 2 > b) i--;
    ib = i;
    jb = b - i * (i + 1) / 2;
}

// ---------------- kernel 1: normalize rows ----------------
__global__ void k_normalize(const float* __restrict__ x) {
    __shared__ float sh[32];
    int t = blockIdx.x;
    const float* row = x + (size_t)t * DD;
    float ss = 0.f;
    for (int i = threadIdx.x; i < DD; i += blockDim.x) {
        float v = row[i];
        ss += v * v;
    }
    ss = blockReduceSum(ss, sh);
    float norm = sqrtf(ss);
    float inv = 1.0f / fmaxf(norm, 1e-12f);
    float* hr = g_h + (size_t)t * DD;
    for (int i = threadIdx.x; i < DD; i += blockDim.x)
        hr[i] = row[i] * inv;
    if (threadIdx.x == 0) {
        g_hn2[t] = ss * inv * inv;   // ||h||^2 after rounding (≈1)
        g_maxQ[t] = -3.0e38f;
    }
}

// ---------------- kernel 2: sim = h h^T on causal blocks ----------------
__global__ void k_gemm_sim() {
    int ib, jb;
    triDecode(blockIdx.x, ib, jb);
    __shared__ float As[BK][BM + 1];
    __shared__ float Bs[BK][BN + 1];
    int tid = threadIdx.x;
    int tx = tid & 15, ty = tid >> 4;
    int rowA = ib * BM, rowB = jb * BN;
    float acc[8][8];
#pragma unroll
    for (int i = 0; i < 8; i++)
#pragma unroll
        for (int j = 0; j < 8; j++) acc[i][j] = 0.f;

    for (int k0 = 0; k0 < DD; k0 += BK) {
#pragma unroll
        for (int i = tid; i < BM * BK; i += 256) {
            int r = i >> 4, c = i & 15;
            As[c][r] = g_h[(size_t)(rowA + r) * DD + k0 + c];
        }
#pragma unroll
        for (int i = tid; i < BN * BK; i += 256) {
            int r = i >> 4, c = i & 15;
            Bs[c][r] = g_h[(size_t)(rowB + r) * DD + k0 + c];
        }
        __syncthreads();
#pragma unroll
        for (int kk = 0; kk < BK; kk++) {
            float a[8], b[8];
#pragma unroll
            for (int i = 0; i < 8; i++) a[i] = As[kk][ty * 8 + i];
#pragma unroll
            for (int j = 0; j < 8; j++) b[j] = Bs[kk][tx * 8 + j];
#pragma unroll
            for (int i = 0; i < 8; i++)
#pragma unroll
                for (int j = 0; j < 8; j++) acc[i][j] += a[i] * b[j];
        }
        __syncthreads();
    }
#pragma unroll
    for (int i = 0; i < 8; i++) {
        size_t base = (size_t)(rowA + ty * 8 + i) * TT + rowB + tx * 8;
#pragma unroll
        for (int j = 0; j < 8; j++) g_sim[base + j] = acc[i][j];
    }
}

// ---------------- kernel 3: causal decayed softmax per row (in place) ------
__global__ void k_softmax() {
    __shared__ float sh[32];
    int t = blockIdx.x;
    float* row = g_sim + (size_t)t * TT;
    int n = t + 1;
    const float sqrt_d = sqrtf((float)DD);
    // pass 1: logits + max
    float lmax = -3.0e38f;
    for (int s = threadIdx.x; s < n; s += blockDim.x) {
        float tds = (float)(t - s);
        float denom = sqrt_d * expf(0.1f * tds) + 1e-8f;
        float l = row[s] / denom;
        row[s] = l;
        lmax = fmaxf(lmax, l);
    }
    lmax = blockReduceMax(lmax, sh);
    // pass 2: exp + sum
    float lsum = 0.f;
    for (int s = threadIdx.x; s < n; s += blockDim.x) {
        float e = expf(row[s] - lmax);
        row[s] = e;
        lsum += e;
    }
    lsum = blockReduceSum(lsum, sh);
    float inv = 1.0f / lsum;
    // pass 3: normalize + zero tail (so alpha@h can read full rows)
    for (int s = threadIdx.x; s < n; s += blockDim.x) row[s] *= inv;
    for (int s = n + threadIdx.x; s < TT; s += blockDim.x) row[s] = 0.f;
}

// ---------------- kernel 4: g = alpha @ h (K truncated causally) ----------
__global__ void k_gemm_g() {
    int jb = blockIdx.x;          // 0..6 over D
    int ib = blockIdx.y;          // 0..31 over T
    __shared__ float As[BK][BM + 1];
    __shared__ float Bs[BK][BN + 1];
    int tid = threadIdx.x;
    int tx = tid & 15, ty = tid >> 4;
    int rowA = ib * BM, colB = jb * BN;
    int kmax = (ib + 1) * BM;     // alpha[t,s]=0 for s>t; skip all-zero K tiles
    float acc[8][8];
#pragma unroll
    for (int i = 0; i < 8; i++)
#pragma unroll
        for (int j = 0; j < 8; j++) acc[i][j] = 0.f;

    for (int k0 = 0; k0 < kmax; k0 += BK) {
#pragma unroll
        for (int i = tid; i < BM * BK; i += 256) {
            int r = i >> 4, c = i & 15;
            As[c][r] = g_sim[(size_t)(rowA + r) * TT + k0 + c];
        }
#pragma unroll
        for (int i = tid; i < BK * BN; i += 256) {
            int r = i >> 7, c = i & 127;      // BN=128
            Bs[r][c] = g_h[(size_t)(k0 + r) * DD + colB + c];
        }
        __syncthreads();
#pragma unroll
        for (int kk = 0; kk < BK; kk++) {
            float a[8], b[8];
#pragma unroll
            for (int i = 0; i < 8; i++) a[i] = As[kk][ty * 8 + i];
#pragma unroll
            for (int j = 0; j < 8; j++) b[j] = Bs[kk][tx * 8 + j];
#pragma unroll
            for (int i = 0; i < 8; i++)
#pragma unroll
                for (int j = 0; j < 8; j++) acc[i][j] += a[i] * b[j];
        }
        __syncthreads();
    }
#pragma unroll
    for (int i = 0; i < 8; i++) {
        size_t base = (size_t)(rowA + ty * 8 + i) * DD + colB + tx * 8;
#pragma unroll
        for (int j = 0; j < 8; j++) g_g[base + j] = acc[i][j];
    }
}

// ---------------- kernel 5: cross = g h^T with fused causal max-reduce -----
// maxQ[t] = max_{s<=t} ( hn2[s] - 2 * g_t . h_s )
__global__ void k_crossmax() {
    int ib, jb;
    triDecode(blockIdx.x, ib, jb);
    __shared__ float As[BK][BM + 1];
    __shared__ float Bs[BK][BN + 1];
    __shared__ float hn2s[BN];
    __shared__ float red[BM][16];
    int tid = threadIdx.x;
    int tx = tid & 15, ty = tid >> 4;
    int rowA = ib * BM, rowB = jb * BN;
    float acc[8][8];
#pragma unroll
    for (int i = 0; i < 8; i++)
#pragma unroll
        for (int j = 0; j < 8; j++) acc[i][j] = 0.f;

    if (tid < BN) hn2s[tid] = g_hn2[rowB + tid];

    for (int k0 = 0; k0 < DD; k0 += BK) {
#pragma unroll
        for (int i = tid; i < BM * BK; i += 256) {
            int r = i >> 4, c = i & 15;
            As[c][r] = g_g[(size_t)(rowA + r) * DD + k0 + c];
        }
#pragma unroll
        for (int i = tid; i < BN * BK; i += 256) {
            int r = i >> 4, c = i & 15;
            Bs[c][r] = g_h[(size_t)(rowB + r) * DD + k0 + c];
        }
        __syncthreads();
#pragma unroll
        for (int kk = 0; kk < BK; kk++) {
            float a[8], b[8];
#pragma unroll
            for (int i = 0; i < 8; i++) a[i] = As[kk][ty * 8 + i];
#pragma unroll
            for (int j = 0; j < 8; j++) b[j] = Bs[kk][tx * 8 + j];
#pragma unroll
            for (int i = 0; i < 8; i++)
#pragma unroll
                for (int j = 0; j < 8; j++) acc[i][j] += a[i] * b[j];
        }
        __syncthreads();
    }

    // epilogue: per-row max of (hn2[s] - 2*cross) over valid s<=t
#pragma unroll
    for (int i = 0; i < 8; i++) {
        int t = rowA + ty * 8 + i;
        float rmax = -3.0e38f;
#pragma unroll
        for (int j = 0; j < 8; j++) {
            int s = rowB + tx * 8 + j;
            if (s <= t) {
                float q = hn2s[tx * 8 + j] - 2.0f * acc[i][j];
                rmax = fmaxf(rmax, q);
            }
        }
        red[ty * 8 + i][tx] = rmax;
    }
    __syncthreads();
    if (tid < BM) {
        float m = red[tid][0];
#pragma unroll
        for (int c = 1; c < 16; c++) m = fmaxf(m, red[tid][c]);
        if (m > -2.0e38f) atomicMaxF(&g_maxQ[rowA + tid], m);
    }
}

// ---------------- kernel 6: final elementwise ------------------------------
__global__ void k_final(const float* __restrict__ m_t, const float* __restrict__ c_t,
                        const float* __restrict__ d_t, const float* __restrict__ mu,
                        float* __restrict__ out) {
    __shared__ float sh[32];
    int t = blockIdx.x;
    const float* hr = g_h + (size_t)t * DD;
    const float* gr = g_g + (size_t)t * DD;
    float dd = 0.f, gn2 = 0.f;
    for (int i = threadIdx.x; i < DD; i += blockDim.x) {
        float hv = hr[i], gv = gr[i];
        float df = hv - gv;
        dd += df * df;
        gn2 += gv * gv;
    }
    dd = blockReduceSum(dd, sh);
    gn2 = blockReduceSum(gn2, sh);
    if (threadIdx.x == 0) {
        float dist = sqrtf(fmaxf(dd, 1e-24f));
        float dm2 = fmaxf(gn2 + g_maxQ[t], 1e-24f);
        float dmax = sqrtf(dm2);
        if (dmax < 1e-6f) dmax = 1.0f;
        float ratio = dist / (dmax + 1e-8f);
        float stab = 1.0f - 0.3f * c_t[t] + 0.2f * d_t[t];
        float xi = 1.0f - mu[0] * m_t[t];
        float v = ratio * stab * xi;
        out[t] = fminf(fmaxf(v, 0.0f), 1.0f);
    }
}

// ---------------- launch ----------------------------------------------------
extern "C" void kernel_launch(void* const* d_in, const int* in_sizes, int n_in,
                              void* d_out, int out_size) {
    const float* x   = (const float*)d_in[0];
    const float* m_t = (const float*)d_in[1];
    const float* c_t = (const float*)d_in[2];
    const float* d_t = (const float*)d_in[3];
    const float* mu  = (const float*)d_in[4];
    float* out = (float*)d_out;

    k_normalize<<<TT, 256>>>(x);
    k_gemm_sim<<<NPAIR, 256>>>();
    k_softmax<<<TT, 256>>>();
    k_gemm_g<<<dim3(DD / BN, NBLK), 256>>>();
    k_crossmax<<<NPAIR, 256>>>();
    k_final<<<TT, 256>>>(m_t, c_t, d_t, mu, out);
}

// round 3
// speedup vs baseline: 1.2307x; 1.2307x over previous
#include <cuda_runtime.h>
#include <math.h>

#define TT 4096
#define DD 896

constexpr int BM = 128, BN = 128, BK = 16;
constexpr int NBLK  = TT / BM;                 // 32
constexpr int NPAIR = NBLK * (NBLK + 1) / 2;   // 528 causal block pairs
constexpr int NKT_FULL = DD / BK;              // 56

// ---------------- scratch (device globals: allocation-free) ----------------
__device__ float g_h[(size_t)TT * DD];      // normalized hidden states (fp32)
__device__ float g_g[(size_t)TT * DD];      // anchor g(t) (fp32)
__device__ float g_sim[(size_t)TT * TT];    // sim -> alpha (in place)
__device__ float g_hn2[TT];                 // ||h_s||^2
__device__ float g_maxQ[TT];                // max_{s<=t} (hn2[s] - 2*cross[t,s])

// ---------------- small helpers ----------------
__device__ __forceinline__ unsigned f2tf(float f) {
    unsigned u;
    asm("cvt.rna.tf32.f32 %0, %1;" : "=r"(u) : "f"(f));
    return u;
}

// 3xTF32 split: x = hi + lo, hi = tf32(x), lo = tf32(x - hi)
__device__ __forceinline__ void tfsplit(float f, unsigned& hi, unsigned& lo) {
    hi = f2tf(f);
    lo = f2tf(f - __uint_as_float(hi));
}

__device__ __forceinline__ void mma8(float* d, const unsigned* a, const unsigned* b) {
    asm volatile(
        "mma.sync.aligned.m16n8k8.row.col.f32.tf32.tf32.f32 "
        "{%0,%1,%2,%3}, {%4,%5,%6,%7}, {%8,%9}, {%0,%1,%2,%3};\n"
        : "+f"(d[0]), "+f"(d[1]), "+f"(d[2]), "+f"(d[3])
        : "r"(a[0]), "r"(a[1]), "r"(a[2]), "r"(a[3]),
          "r"(b[0]), "r"(b[1]));
}

__device__ __forceinline__ float blockReduceSum(float v, float* sh) {
    int lane = threadIdx.x & 31, w = threadIdx.x >> 5;
#pragma unroll
    for (int o = 16; o; o >>= 1) v += __shfl_xor_sync(0xffffffffu, v, o);
    __syncthreads();
    if (lane == 0) sh[w] = v;
    __syncthreads();
    if (threadIdx.x == 0) {
        float s = 0.f;
        int nw = (blockDim.x + 31) >> 5;
        for (int i = 0; i < nw; i++) s += sh[i];
        sh[0] = s;
    }
    __syncthreads();
    return sh[0];
}

__device__ __forceinline__ float blockReduceMax(float v, float* sh) {
    int lane = threadIdx.x & 31, w = threadIdx.x >> 5;
#pragma unroll
    for (int o = 16; o; o >>= 1) v = fmaxf(v, __shfl_xor_sync(0xffffffffu, v, o));
    __syncthreads();
    if (lane == 0) sh[w] = v;
    __syncthreads();
    if (threadIdx.x == 0) {
        float m = -3.0e38f;
        int nw = (blockDim.x + 31) >> 5;
        for (int i = 0; i < nw; i++) m = fmaxf(m, sh[i]);
        sh[0] = m;
    }
    __syncthreads();
    return sh[0];
}

__device__ __forceinline__ void atomicMaxF(float* addr, float val) {
    int old = __float_as_int(*addr);
    while (__int_as_float(old) < val) {
        int assumed = old;
        old = atomicCAS((int*)addr, assumed, __float_as_int(val));
        if (old == assumed) break;
    }
}

__device__ __forceinline__ void triDecode(int b, int& ib, int& jb) {
    int i = (int)floorf((sqrtf(8.0f * (float)b + 1.0f) - 1.0f) * 0.5f);
    while ((i + 1) * (i + 2) / 2 <= b) i++;
    while (i * (i + 1) / 2 > b) i--;
    ib = i;
    jb = b - i * (i + 1) / 2;
}

// ============================================================================
// Fragment-packed staging (BK=16 -> 2 k-steps of 8 per tile).
// A smem: [8 mtiles][2 ksteps][32 lanes][4 regs]  (2048 u32 = 8KB per buffer)
// B smem: [16 ntiles][2 ksteps][32 lanes][2 regs] (2048 u32 = 8KB per buffer)
// mma m16n8k8 row.col lane map (gr=lane>>2, gc=lane&3):
//   A: a0=(gr,gc) a1=(gr+8,gc) a2=(gr,gc+4) a3=(gr+8,gc+4)
//   B: b0=(k=gc,n=gr) b1=(k=gc+4,n=gr)
//   D: c0=(gr,2gc) c1=(gr,2gc+1) c2=(gr+8,2gc) c3=(gr+8,2gc+1)
// ============================================================================

// scatter float4 at (row r, k-col c4*4) of a [128 x 16] A tile (hi+lo)
__device__ __forceinline__ void stsA(unsigned* Ah, unsigned* Al, int r, int c4, float4 v) {
    int c = c4 * 4;
    int mt = r >> 4, rr = r & 15, ks = c >> 3, kk = c & 7;   // kk in {0,4}
    int j = ((kk >= 4) ? 2 : 0) + ((rr >= 8) ? 1 : 0);
    int base = ((mt * 2 + ks) << 7) + ((rr & 7) << 4) + j;
    unsigned h, l;
    tfsplit(v.x, h, l); Ah[base + 0]  = h; Al[base + 0]  = l;
    tfsplit(v.y, h, l); Ah[base + 4]  = h; Al[base + 4]  = l;
    tfsplit(v.z, h, l); Ah[base + 8]  = h; Al[base + 8]  = l;
    tfsplit(v.w, h, l); Ah[base + 12] = h; Al[base + 12] = l;
}

// scatter float4 at (n row, k-col c4*4) of a [128n x 16k] B tile (n-major)
__device__ __forceinline__ void stsB_nmajor(unsigned* Bh, unsigned* Bl, int n, int c4, float4 v) {
    int c = c4 * 4;
    int nt = n >> 3, nn = n & 7, ks = c >> 3, kk = c & 7;    // kk in {0,4}
    int j = (kk >= 4) ? 1 : 0;
    int base = ((nt * 2 + ks) << 6) + (nn << 3) + j;
    unsigned h, l;
    tfsplit(v.x, h, l); Bh[base + 0] = h; Bl[base + 0] = l;
    tfsplit(v.y, h, l); Bh[base + 2] = h; Bl[base + 2] = l;
    tfsplit(v.z, h, l); Bh[base + 4] = h; Bl[base + 4] = l;
    tfsplit(v.w, h, l); Bh[base + 6] = h; Bl[base + 6] = l;
}

// scatter float4 at (k row, n-col n4*4) of a [16k x 128n] B tile (k-major)
__device__ __forceinline__ void stsB_kmajor(unsigned* Bh, unsigned* Bl, int k, int n4, float4 v) {
    int n = n4 * 4;
    int nt = n >> 3, ks = k >> 3, kk = k & 7;
    int j = (kk >= 4) ? 1 : 0;
    int base = ((nt * 2 + ks) << 6) + (((n & 7) * 4 + (kk & 3)) << 1) + j;
    unsigned h, l;
    tfsplit(v.x, h, l); Bh[base + 0]  = h; Bl[base + 0]  = l;
    tfsplit(v.y, h, l); Bh[base + 8]  = h; Bl[base + 8]  = l;
    tfsplit(v.z, h, l); Bh[base + 16] = h; Bl[base + 16] = l;
    tfsplit(v.w, h, l); Bh[base + 24] = h; Bl[base + 24] = l;
}

// compute inner product over one staged k-tile with 3xTF32 compensation
#define MMA_TILE_BODY(Ah, Al, Bh, Bl, acc, wm, wn, lane)                               \
    _Pragma("unroll")                                                                  \
    for (int ks = 0; ks < 2; ks++) {                                                   \
        unsigned bh[4][2], bl[4][2];                                                   \
        _Pragma("unroll")                                                              \
        for (int j = 0; j < 4; j++) {                                                  \
            *(uint2*)bh[j] = *(const uint2*)&Bh[((((wn) * 4 + j) * 2 + ks) * 32 + (lane)) * 2]; \
            *(uint2*)bl[j] = *(const uint2*)&Bl[((((wn) * 4 + j) * 2 + ks) * 32 + (lane)) * 2]; \
        }                                                                              \
        _Pragma("unroll")                                                              \
        for (int i = 0; i < 4; i++) {                                                  \
            unsigned ah[4], al[4];                                                     \
            *(uint4*)ah = *(const uint4*)&Ah[((((wm) * 4 + i) * 2 + ks) * 32 + (lane)) * 4]; \
            *(uint4*)al = *(const uint4*)&Al[((((wm) * 4 + i) * 2 + ks) * 32 + (lane)) * 4]; \
            _Pragma("unroll")                                                          \
            for (int j = 0; j < 4; j++) {                                              \
                mma8(acc[i][j], ah, bl[j]);                                            \
                mma8(acc[i][j], al, bh[j]);                                            \
                mma8(acc[i][j], ah, bh[j]);                                            \
            }                                                                          \
        }                                                                              \
    }

// ---------------- kernel 1: normalize rows ----------------
__global__ void k_normalize(const float* __restrict__ x) {
    __shared__ float sh[32];
    int t = blockIdx.x;
    const float* row = x + (size_t)t * DD;
    float ss = 0.f;
    for (int i = threadIdx.x; i < DD; i += blockDim.x) {
        float v = row[i];
        ss += v * v;
    }
    ss = blockReduceSum(ss, sh);
    float norm = sqrtf(ss);
    float inv = 1.0f / fmaxf(norm, 1e-12f);
    float* hr = g_h + (size_t)t * DD;
    for (int i = threadIdx.x; i < DD; i += blockDim.x)
        hr[i] = row[i] * inv;
    if (threadIdx.x == 0) {
        g_hn2[t] = ss * inv * inv;
        g_maxQ[t] = -3.0e38f;
    }
}

// ---------------- kernel 2: sim = h h^T on causal blocks (3xTF32) ----------
__global__ void __launch_bounds__(256) k_gemm_sim() {
    __shared__ __align__(16) unsigned Ah[8 * 2 * 32 * 4], Al[8 * 2 * 32 * 4];
    __shared__ __align__(16) unsigned Bh[16 * 2 * 32 * 2], Bl[16 * 2 * 32 * 2];
    int ib, jb;
    triDecode(blockIdx.x, ib, jb);
    int tid = threadIdx.x, lane = tid & 31, warp = tid >> 5;
    int wm = warp >> 2, wn = warp & 3;
    int gr = lane >> 2, gc = lane & 3;
    int rowA = ib * BM, rowB = jb * BN;

    float acc[4][4][4];
#pragma unroll
    for (int i = 0; i < 4; i++)
#pragma unroll
        for (int j = 0; j < 4; j++)
#pragma unroll
            for (int e = 0; e < 4; e++) acc[i][j][e] = 0.f;

    float4 pa[2], pb[2];
#pragma unroll
    for (int it = 0; it < 2; it++) {
        int idx = tid + it * 256;
        int r = idx >> 2, c4 = idx & 3;
        pa[it] = *(const float4*)(g_h + (size_t)(rowA + r) * DD + c4 * 4);
        pb[it] = *(const float4*)(g_h + (size_t)(rowB + r) * DD + c4 * 4);
    }

    for (int kt = 0; kt < NKT_FULL; kt++) {
#pragma unroll
        for (int it = 0; it < 2; it++) {
            int idx = tid + it * 256;
            int r = idx >> 2, c4 = idx & 3;
            stsA(Ah, Al, r, c4, pa[it]);
            stsB_nmajor(Bh, Bl, r, c4, pb[it]);
        }
        __syncthreads();
        if (kt + 1 < NKT_FULL) {
            int k0 = (kt + 1) * BK;
#pragma unroll
            for (int it = 0; it < 2; it++) {
                int idx = tid + it * 256;
                int r = idx >> 2, c4 = idx & 3;
                pa[it] = *(const float4*)(g_h + (size_t)(rowA + r) * DD + k0 + c4 * 4);
                pb[it] = *(const float4*)(g_h + (size_t)(rowB + r) * DD + k0 + c4 * 4);
            }
        }
        MMA_TILE_BODY(Ah, Al, Bh, Bl, acc, wm, wn, lane)
        __syncthreads();
    }

#pragma unroll
    for (int i = 0; i < 4; i++) {
        int t = rowA + (wm * 4 + i) * 16 + gr;
#pragma unroll
        for (int j = 0; j < 4; j++) {
            int s = rowB + (wn * 4 + j) * 8 + gc * 2;
            *(float2*)&g_sim[(size_t)t * TT + s]       = make_float2(acc[i][j][0], acc[i][j][1]);
            *(float2*)&g_sim[(size_t)(t + 8) * TT + s] = make_float2(acc[i][j][2], acc[i][j][3]);
        }
    }
}

// ---------------- kernel 3: causal decayed softmax per row (in place) ------
__global__ void k_softmax() {
    __shared__ float sh[32];
    int t = blockIdx.x;
    float* row = g_sim + (size_t)t * TT;
    int n = t + 1;
    const float sqrt_d = sqrtf((float)DD);
    float lmax = -3.0e38f;
    for (int s = threadIdx.x; s < n; s += blockDim.x) {
        float tds = (float)(t - s);
        float denom = sqrt_d * expf(0.1f * tds) + 1e-8f;
        float l = row[s] / denom;
        row[s] = l;
        lmax = fmaxf(lmax, l);
    }
    lmax = blockReduceMax(lmax, sh);
    float lsum = 0.f;
    for (int s = threadIdx.x; s < n; s += blockDim.x) {
        float e = expf(row[s] - lmax);
        row[s] = e;
        lsum += e;
    }
    lsum = blockReduceSum(lsum, sh);
    float inv = 1.0f / lsum;
    for (int s = threadIdx.x; s < n; s += blockDim.x) row[s] *= inv;
    for (int s = n + threadIdx.x; s < TT; s += blockDim.x) row[s] = 0.f;
}

// ---------------- kernel 4: g = alpha @ h (3xTF32, causal K-trunc) ---------
__global__ void __launch_bounds__(256) k_gemm_g() {
    __shared__ __align__(16) unsigned Ah[8 * 2 * 32 * 4], Al[8 * 2 * 32 * 4];
    __shared__ __align__(16) unsigned Bh[16 * 2 * 32 * 2], Bl[16 * 2 * 32 * 2];
    int jbD = blockIdx.x;
    int ib  = blockIdx.y;
    int tid = threadIdx.x, lane = tid & 31, warp = tid >> 5;
    int wm = warp >> 2, wn = warp & 3;
    int gr = lane >> 2, gc = lane & 3;
    int rowA = ib * BM, colB = jbD * BN;
    int nkt = (ib + 1) * (BM / BK);  // causal: alpha zero beyond t

    float acc[4][4][4];
#pragma unroll
    for (int i = 0; i < 4; i++)
#pragma unroll
        for (int j = 0; j < 4; j++)
#pragma unroll
            for (int e = 0; e < 4; e++) acc[i][j][e] = 0.f;

    float4 pa[2], pb[2];
#pragma unroll
    for (int it = 0; it < 2; it++) {
        int idx = tid + it * 256;
        int rA = idx >> 2, c4 = idx & 3;
        pa[it] = *(const float4*)(g_sim + (size_t)(rowA + rA) * TT + c4 * 4);
        int kB = idx >> 5, n4 = idx & 31;
        pb[it] = *(const float4*)(g_h + (size_t)kB * DD + colB + n4 * 4);
    }

    for (int kt = 0; kt < nkt; kt++) {
#pragma unroll
        for (int it = 0; it < 2; it++) {
            int idx = tid + it * 256;
            int rA = idx >> 2, c4 = idx & 3;
            stsA(Ah, Al, rA, c4, pa[it]);
            int kB = idx >> 5, n4 = idx & 31;
            stsB_kmajor(Bh, Bl, kB, n4, pb[it]);
        }
        __syncthreads();
        if (kt + 1 < nkt) {
            int k0 = (kt + 1) * BK;
#pragma unroll
            for (int it = 0; it < 2; it++) {
                int idx = tid + it * 256;
                int rA = idx >> 2, c4 = idx & 3;
                pa[it] = *(const float4*)(g_sim + (size_t)(rowA + rA) * TT + k0 + c4 * 4);
                int kB = idx >> 5, n4 = idx & 31;
                pb[it] = *(const float4*)(g_h + (size_t)(k0 + kB) * DD + colB + n4 * 4);
            }
        }
        MMA_TILE_BODY(Ah, Al, Bh, Bl, acc, wm, wn, lane)
        __syncthreads();
    }

#pragma unroll
    for (int i = 0; i < 4; i++) {
        int t = rowA + (wm * 4 + i) * 16 + gr;
#pragma unroll
        for (int j = 0; j < 4; j++) {
            int d = colB + (wn * 4 + j) * 8 + gc * 2;
            *(float2*)&g_g[(size_t)t * DD + d]       = make_float2(acc[i][j][0], acc[i][j][1]);
            *(float2*)&g_g[(size_t)(t + 8) * DD + d] = make_float2(acc[i][j][2], acc[i][j][3]);
        }
    }
}

// ---------------- kernel 5: cross = g h^T + fused causal max-reduce --------
__global__ void __launch_bounds__(256) k_crossmax() {
    __shared__ __align__(16) unsigned Ah[8 * 2 * 32 * 4], Al[8 * 2 * 32 * 4];
    __shared__ __align__(16) unsigned Bh[16 * 2 * 32 * 2], Bl[16 * 2 * 32 * 2];
    __shared__ float hn2s[BN];
    __shared__ float red[BM][4];
    int ib, jb;
    triDecode(blockIdx.x, ib, jb);
    int tid = threadIdx.x, lane = tid & 31, warp = tid >> 5;
    int wm = warp >> 2, wn = warp & 3;
    int gr = lane >> 2, gc = lane & 3;
    int rowA = ib * BM, rowB = jb * BN;

    if (tid < BN) hn2s[tid] = g_hn2[rowB + tid];

    float acc[4][4][4];
#pragma unroll
    for (int i = 0; i < 4; i++)
#pragma unroll
        for (int j = 0; j < 4; j++)
#pragma unroll
            for (int e = 0; e < 4; e++) acc[i][j][e] = 0.f;

    float4 pa[2], pb[2];
#pragma unroll
    for (int it = 0; it < 2; it++) {
        int idx = tid + it * 256;
        int r = idx >> 2, c4 = idx & 3;
        pa[it] = *(const float4*)(g_g + (size_t)(rowA + r) * DD + c4 * 4);
        pb[it] = *(const float4*)(g_h + (size_t)(rowB + r) * DD + c4 * 4);
    }

    for (int kt = 0; kt < NKT_FULL; kt++) {
#pragma unroll
        for (int it = 0; it < 2; it++) {
            int idx = tid + it * 256;
            int r = idx >> 2, c4 = idx & 3;
            stsA(Ah, Al, r, c4, pa[it]);
            stsB_nmajor(Bh, Bl, r, c4, pb[it]);
        }
        __syncthreads();
        if (kt + 1 < NKT_FULL) {
            int k0 = (kt + 1) * BK;
#pragma unroll
            for (int it = 0; it < 2; it++) {
                int idx = tid + it * 256;
                int r = idx >> 2, c4 = idx & 3;
                pa[it] = *(const float4*)(g_g + (size_t)(rowA + r) * DD + k0 + c4 * 4);
                pb[it] = *(const float4*)(g_h + (size_t)(rowB + r) * DD + k0 + c4 * 4);
            }
        }
        MMA_TILE_BODY(Ah, Al, Bh, Bl, acc, wm, wn, lane)
        __syncthreads();
    }

    // epilogue: per-row max of (hn2[s] - 2*cross) over valid s<=t
#pragma unroll
    for (int i = 0; i < 4; i++) {
        int t0 = rowA + (wm * 4 + i) * 16 + gr;
        float m0 = -3.0e38f, m1 = -3.0e38f;
#pragma unroll
        for (int j = 0; j < 4; j++) {
#pragma unroll
            for (int e = 0; e < 2; e++) {
                int sl = (wn * 4 + j) * 8 + gc * 2 + e;
                int s = rowB + sl;
                float hn = hn2s[sl];
                float q0 = hn - 2.0f * acc[i][j][e];
                float q1 = hn - 2.0f * acc[i][j][2 + e];
                if (s <= t0)     m0 = fmaxf(m0, q0);
                if (s <= t0 + 8) m1 = fmaxf(m1, q1);
            }
        }
#pragma unroll
        for (int o = 1; o < 4; o <<= 1) {
            m0 = fmaxf(m0, __shfl_xor_sync(0xffffffffu, m0, o));
            m1 = fmaxf(m1, __shfl_xor_sync(0xffffffffu, m1, o));
        }
        if (gc == 0) {
            red[t0 - rowA][wn]     = m0;
            red[t0 - rowA + 8][wn] = m1;
        }
    }
    __syncthreads();
    if (tid < BM) {
        float m = fmaxf(fmaxf(red[tid][0], red[tid][1]), fmaxf(red[tid][2], red[tid][3]));
        if (m > -2.0e38f) atomicMaxF(&g_maxQ[rowA + tid], m);
    }
}

// ---------------- kernel 6: final elementwise ------------------------------
__global__ void k_final(const float* __restrict__ m_t, const float* __restrict__ c_t,
                        const float* __restrict__ d_t, const float* __restrict__ mu,
                        float* __restrict__ out) {
    __shared__ float sh[32];
    int t = blockIdx.x;
    const float* hr = g_h + (size_t)t * DD;
    const float* gr = g_g + (size_t)t * DD;
    float dd = 0.f, gn2 = 0.f;
    for (int i = threadIdx.x; i < DD; i += blockDim.x) {
        float hv = hr[i], gv = gr[i];
        float df = hv - gv;
        dd += df * df;
        gn2 += gv * gv;
    }
    dd = blockReduceSum(dd, sh);
    gn2 = blockReduceSum(gn2, sh);
    if (threadIdx.x == 0) {
        float dist = sqrtf(fmaxf(dd, 1e-24f));
        float dm2 = fmaxf(gn2 + g_maxQ[t], 1e-24f);
        float dmax = sqrtf(dm2);
        if (dmax < 1e-6f) dmax = 1.0f;
        float ratio = dist / (dmax + 1e-8f);
        float stab = 1.0f - 0.3f * c_t[t] + 0.2f * d_t[t];
        float xi = 1.0f - mu[0] * m_t[t];
        float v = ratio * stab * xi;
        out[t] = fminf(fmaxf(v, 0.0f), 1.0f);
    }
}

// ---------------- launch ----------------------------------------------------
extern "C" void kernel_launch(void* const* d_in, const int* in_sizes, int n_in,
                              void* d_out, int out_size) {
    const float* x   = (const float*)d_in[0];
    const float* m_t = (const float*)d_in[1];
    const float* c_t = (const float*)d_in[2];
    const float* d_t = (const float*)d_in[3];
    const float* mu  = (const float*)d_in[4];
    float* out = (float*)d_out;

    k_normalize<<<TT, 256>>>(x);
    k_gemm_sim<<<NPAIR, 256>>>();
    k_softmax<<<TT, 256>>>();
    k_gemm_g<<<dim3(DD / BN, NBLK), 256>>>();
    k_crossmax<<<NPAIR, 256>>>();
    k_final<<<TT, 256>>>(m_t, c_t, d_t, mu, out);
}

// round 5
// speedup vs baseline: 2.8243x; 2.2949x over previous
#include <cuda_runtime.h>
#include <cstdint>
#include <math.h>

#define TT 4096
#define DD 896

constexpr int BM = 128, BN = 64, BK = 32;
constexpr int NROWB = TT / BM;               // 32 row-blocks of 128
constexpr int NPAIRB = NROWB * (NROWB + 1);  // 1056 causal (128x64) blocks
constexpr int NKT_FULL = DD / BK;            // 28

// packed-stage geometry (padded strides for bank-conflict-free staging)
constexpr int A_GRP = 132;                       // words per (mtile,ks) group (128 + 4 pad)
constexpr int B_GRP = 68;                        // words per (ntile,ks) group (64 + 4 pad)
constexpr int OFF_AL = 32 * A_GRP;               // 4224
constexpr int OFF_BH = 2 * 32 * A_GRP;           // 8448
constexpr int OFF_BL = OFF_BH + 32 * B_GRP;      // 10624
constexpr int STAGE_WORDS = OFF_BL + 32 * B_GRP; // 12800 words = 51200 B
constexpr unsigned DSMEM = 2u * STAGE_WORDS * 4u; // 102400 B (2 stages)

// ---------------- scratch (device globals: allocation-free) ----------------
__device__ float g_h[(size_t)TT * DD];
__device__ float g_g[(size_t)TT * DD];
__device__ float g_sim[(size_t)TT * TT];
__device__ float g_hn2[TT];
__device__ float g_maxQ[TT];
__device__ float g_invden[TT];

// ---------------- small helpers ----------------
__device__ __forceinline__ unsigned f2tf(float f) {
    unsigned u;
    asm("cvt.rna.tf32.f32 %0, %1;" : "=r"(u) : "f"(f));
    return u;
}
__device__ __forceinline__ void tfsplit(float f, unsigned& hi, unsigned& lo) {
    hi = f2tf(f);
    lo = f2tf(f - __uint_as_float(hi));
}
__device__ __forceinline__ void mma8(float* d, const unsigned* a, const unsigned* b) {
    asm volatile(
        "mma.sync.aligned.m16n8k8.row.col.f32.tf32.tf32.f32 "
        "{%0,%1,%2,%3}, {%4,%5,%6,%7}, {%8,%9}, {%0,%1,%2,%3};\n"
        : "+f"(d[0]), "+f"(d[1]), "+f"(d[2]), "+f"(d[3])
        : "r"(a[0]), "r"(a[1]), "r"(a[2]), "r"(a[3]),
          "r"(b[0]), "r"(b[1]));
}
__device__ __forceinline__ float blockReduceSum(float v, float* sh) {
    int lane = threadIdx.x & 31, w = threadIdx.x >> 5;
#pragma unroll
    for (int o = 16; o; o >>= 1) v += __shfl_xor_sync(0xffffffffu, v, o);
    __syncthreads();
    if (lane == 0) sh[w] = v;
    __syncthreads();
    if (threadIdx.x == 0) {
        float s = 0.f;
        int nw = (blockDim.x + 31) >> 5;
        for (int i = 0; i < nw; i++) s += sh[i];
        sh[0] = s;
    }
    __syncthreads();
    return sh[0];
}
__device__ __forceinline__ float blockReduceMax(float v, float* sh) {
    int lane = threadIdx.x & 31, w = threadIdx.x >> 5;
#pragma unroll
    for (int o = 16; o; o >>= 1) v = fmaxf(v, __shfl_xor_sync(0xffffffffu, v, o));
    __syncthreads();
    if (lane == 0) sh[w] = v;
    __syncthreads();
    if (threadIdx.x == 0) {
        float m = -3.0e38f;
        int nw = (blockDim.x + 31) >> 5;
        for (int i = 0; i < nw; i++) m = fmaxf(m, sh[i]);
        sh[0] = m;
    }
    __syncthreads();
    return sh[0];
}
__device__ __forceinline__ void atomicMaxF(float* addr, float val) {
    int old = __float_as_int(*addr);
    while (__int_as_float(old) < val) {
        int assumed = old;
        old = atomicCAS((int*)addr, assumed, __float_as_int(val));
        if (old == assumed) break;
    }
}
// triangular decode for 128x64 causal blocks: ib has 2*ib+2 jb's; cum(ib)=ib*(ib+1)
__device__ __forceinline__ void triDecodeB(int b, int& ib, int& jb) {
    int i = (int)((sqrtf(4.0f * (float)b + 1.0f) - 1.0f) * 0.5f);
    while ((i + 1) * (i + 2) <= b) i++;
    while (i * (i + 1) > b) i--;
    ib = i;
    jb = b - i * (i + 1);
}
// per-group lane swizzle for B staging (kills STS bank conflicts)
__device__ __forceinline__ int bswz(int lane, int grp) { return lane ^ (((grp >> 2) & 7) << 1); }

// ---------------- staging: gmem -> regs -> packed smem ----------------
__device__ __forceinline__ void ldA4(const float* __restrict__ src, int ld, int row0, int k0,
                                     float4* pa, int tid) {
#pragma unroll
    for (int it = 0; it < 4; it++) {
        int idx = tid + it * 256;
        pa[it] = *(const float4*)(src + (size_t)(row0 + (idx >> 3)) * ld + k0 + (idx & 7) * 4);
    }
}
__device__ __forceinline__ void stA4(unsigned* S, const float4* pa, int tid) {
    unsigned* Ah = S;
    unsigned* Al = S + OFF_AL;
#pragma unroll
    for (int it = 0; it < 4; it++) {
        int idx = tid + it * 256;
        int r = idx >> 3, c = (idx & 7) * 4;
        int mt = r >> 4, rr = r & 15, ks = c >> 3;
        int jj = (((c & 7) >= 4) ? 2 : 0) + ((rr >= 8) ? 1 : 0);
        int base = (mt * 4 + ks) * A_GRP + ((rr & 7) << 4) + jj;
        const float* v = (const float*)&pa[it];
#pragma unroll
        for (int q = 0; q < 4; q++) {
            unsigned h, l;
            tfsplit(v[q], h, l);
            Ah[base + q * 4] = h;
            Al[base + q * 4] = l;
        }
    }
}
__device__ __forceinline__ void ldBn(const float* __restrict__ src, int ld, int row0, int k0,
                                     float4* pb, int tid) {
#pragma unroll
    for (int it = 0; it < 2; it++) {
        int idx = tid + it * 256;
        pb[it] = *(const float4*)(src + (size_t)(row0 + (idx >> 3)) * ld + k0 + (idx & 7) * 4);
    }
}
__device__ __forceinline__ void stBn(unsigned* S, const float4* pb, int tid) {
    unsigned* Bh = S + OFF_BH;
    unsigned* Bl = S + OFF_BL;
#pragma unroll
    for (int it = 0; it < 2; it++) {
        int idx = tid + it * 256;
        int n = idx >> 3, c = (idx & 7) * 4;
        int nt = n >> 3, nn = n & 7, ks = c >> 3;
        int jj = ((c & 7) >= 4) ? 1 : 0;
        int grp = nt * 4 + ks;
        const float* v = (const float*)&pb[it];
#pragma unroll
        for (int q = 0; q < 4; q++) {
            int word = grp * B_GRP + (bswz(nn * 4 + q, grp) << 1) + jj;
            unsigned h, l;
            tfsplit(v[q], h, l);
            Bh[word] = h;
            Bl[word] = l;
        }
    }
}
// B[n][k] = g_h[k0+k][colB+n] (transposed read for alpha @ h)
__device__ __forceinline__ void ldBk(int k0, int colB, float4* pb, int tid) {
#pragma unroll
    for (int it = 0; it < 2; it++) {
        int idx = tid + it * 256;
        pb[it] = *(const float4*)(g_h + (size_t)(k0 + (idx >> 4)) * DD + colB + (idx & 15) * 4);
    }
}
__device__ __forceinline__ void stBk(unsigned* S, const float4* pb, int tid) {
    unsigned* Bh = S + OFF_BH;
    unsigned* Bl = S + OFF_BL;
#pragma unroll
    for (int it = 0; it < 2; it++) {
        int idx = tid + it * 256;
        int k = idx >> 4, n0 = (idx & 15) * 4;
        int ks = k >> 3, kk = k & 7;
        int jj = (kk >= 4) ? 1 : 0;
        int grp = (n0 >> 3) * 4 + ks;
        const float* v = (const float*)&pb[it];
#pragma unroll
        for (int q = 0; q < 4; q++) {
            int lane = ((n0 + q) & 7) * 4 + (kk & 3);
            int word = grp * B_GRP + (bswz(lane, grp) << 1) + jj;
            unsigned h, l;
            tfsplit(v[q], h, l);
            Bh[word] = h;
            Bl[word] = l;
        }
    }
}

// ---------------- MMA over one staged 32-wide K chunk (3xTF32) -------------
__device__ __forceinline__ void mma_body(const unsigned* S, float acc[4][2][4],
                                         int wm, int wn, int lane) {
    const unsigned* Ah = S;
    const unsigned* Al = S + OFF_AL;
    const unsigned* Bh = S + OFF_BH;
    const unsigned* Bl = S + OFF_BL;
#pragma unroll
    for (int ks = 0; ks < 4; ks++) {
        unsigned bh[2][2], bl[2][2];
#pragma unroll
        for (int j = 0; j < 2; j++) {
            int grp = (wn * 2 + j) * 4 + ks;
            int off = grp * B_GRP + (bswz(lane, grp) << 1);
            *(uint2*)bh[j] = *(const uint2*)&Bh[off];
            *(uint2*)bl[j] = *(const uint2*)&Bl[off];
        }
#pragma unroll
        for (int i = 0; i < 4; i++) {
            int offA = ((wm * 4 + i) * 4 + ks) * A_GRP + lane * 4;
            unsigned ah[4], al[4];
            *(uint4*)ah = *(const uint4*)&Ah[offA];
            *(uint4*)al = *(const uint4*)&Al[offA];
#pragma unroll
            for (int j = 0; j < 2; j++) {
                mma8(acc[i][j], ah, bl[j]);
                mma8(acc[i][j], al, bh[j]);
                mma8(acc[i][j], ah, bh[j]);
            }
        }
    }
}

// ---------------- kernel 1: normalize rows ----------------
__global__ void k_normalize(const float* __restrict__ x) {
    __shared__ float sh[32];
    int t = blockIdx.x;
    const float* row = x + (size_t)t * DD;
    float ss = 0.f;
    for (int i = threadIdx.x; i < DD; i += blockDim.x) {
        float v = row[i];
        ss += v * v;
    }
    ss = blockReduceSum(ss, sh);
    float inv = 1.0f / fmaxf(sqrtf(ss), 1e-12f);
    float* hr = g_h + (size_t)t * DD;
    for (int i = threadIdx.x; i < DD; i += blockDim.x)
        hr[i] = row[i] * inv;
    if (threadIdx.x == 0) {
        g_hn2[t] = ss * inv * inv;
        g_maxQ[t] = -3.0e38f;
    }
}

// ---------------- kernel 1b: 1/denom(delta) table ----------------
__global__ void k_tables() {
    int i = blockIdx.x * 256 + threadIdx.x;
    if (i < TT)
        g_invden[i] = 1.0f / (sqrtf((float)DD) * expf(0.1f * (float)i) + 1e-8f);
}

// ---------------- kernel 2: sim = h h^T (causal 128x64 blocks) -------------
__global__ void __launch_bounds__(256, 2) k_sim() {
    extern __shared__ unsigned dsm[];
    int tid = threadIdx.x, lane = tid & 31, warp = tid >> 5;
    int wm = warp >> 2, wn = warp & 3, gr = lane >> 2, gc = lane & 3;
    int ib, jb;
    triDecodeB(blockIdx.x, ib, jb);
    int rowA = ib * BM, rowB = jb * BN;

    float acc[4][2][4];
#pragma unroll
    for (int i = 0; i < 4; i++)
#pragma unroll
        for (int j = 0; j < 2; j++)
#pragma unroll
            for (int e = 0; e < 4; e++) acc[i][j][e] = 0.f;

    float4 pa[4], pb[2];
    ldA4(g_h, DD, rowA, 0, pa, tid);
    ldBn(g_h, DD, rowB, 0, pb, tid);
    stA4(dsm, pa, tid);
    stBn(dsm, pb, tid);
    ldA4(g_h, DD, rowA, BK, pa, tid);
    ldBn(g_h, DD, rowB, BK, pb, tid);
    __syncthreads();

    for (int kt = 0; kt < NKT_FULL; kt++) {
        if (kt + 1 < NKT_FULL) {
            unsigned* nxt = dsm + ((kt + 1) & 1) * STAGE_WORDS;
            stA4(nxt, pa, tid);
            stBn(nxt, pb, tid);
        }
        if (kt + 2 < NKT_FULL) {
            ldA4(g_h, DD, rowA, (kt + 2) * BK, pa, tid);
            ldBn(g_h, DD, rowB, (kt + 2) * BK, pb, tid);
        }
        mma_body(dsm + (kt & 1) * STAGE_WORDS, acc, wm, wn, lane);
        __syncthreads();
    }

#pragma unroll
    for (int i = 0; i < 4; i++) {
        int t = rowA + (wm * 4 + i) * 16 + gr;
#pragma unroll
        for (int j = 0; j < 2; j++) {
            int s = rowB + (wn * 2 + j) * 8 + gc * 2;
            *(float2*)&g_sim[(size_t)t * TT + s]       = make_float2(acc[i][j][0], acc[i][j][1]);
            *(float2*)&g_sim[(size_t)(t + 8) * TT + s] = make_float2(acc[i][j][2], acc[i][j][3]);
        }
    }
}

// ---------------- kernel 3: causal decayed softmax per row -----------------
__global__ void k_softmax() {
    __shared__ float sh[32];
    int t = blockIdx.x;
    float* row = g_sim + (size_t)t * TT;
    int n = t + 1;
    float lmax = -3.0e38f;
    for (int s = threadIdx.x; s < n; s += blockDim.x) {
        float l = row[s] * g_invden[t - s];
        row[s] = l;
        lmax = fmaxf(lmax, l);
    }
    lmax = blockReduceMax(lmax, sh);
    float lsum = 0.f;
    for (int s = threadIdx.x; s < n; s += blockDim.x) {
        float e = __expf(row[s] - lmax);
        row[s] = e;
        lsum += e;
    }
    lsum = blockReduceSum(lsum, sh);
    float inv = 1.0f / lsum;
    for (int s = threadIdx.x; s < n; s += blockDim.x) row[s] *= inv;
    int zend = ((t >> 7) + 1) * 128;   // g-GEMM only reads up to block boundary
    for (int s = n + threadIdx.x; s < zend; s += blockDim.x) row[s] = 0.f;
}

// ---------------- kernel 4: g = alpha @ h (causal K-trunc) -----------------
__global__ void __launch_bounds__(256, 2) k_g() {
    extern __shared__ unsigned dsm[];
    int tid = threadIdx.x, lane = tid & 31, warp = tid >> 5;
    int wm = warp >> 2, wn = warp & 3, gr = lane >> 2, gc = lane & 3;
    int jbD = blockIdx.x, ib = blockIdx.y;
    int rowA = ib * BM, colB = jbD * BN;
    int nkt = (ib + 1) * 4;   // alpha zero beyond causal boundary

    float acc[4][2][4];
#pragma unroll
    for (int i = 0; i < 4; i++)
#pragma unroll
        for (int j = 0; j < 2; j++)
#pragma unroll
            for (int e = 0; e < 4; e++) acc[i][j][e] = 0.f;

    float4 pa[4], pb[2];
    ldA4(g_sim, TT, rowA, 0, pa, tid);
    ldBk(0, colB, pb, tid);
    stA4(dsm, pa, tid);
    stBk(dsm, pb, tid);
    ldA4(g_sim, TT, rowA, BK, pa, tid);
    ldBk(BK, colB, pb, tid);
    __syncthreads();

    for (int kt = 0; kt < nkt; kt++) {
        if (kt + 1 < nkt) {
            unsigned* nxt = dsm + ((kt + 1) & 1) * STAGE_WORDS;
            stA4(nxt, pa, tid);
            stBk(nxt, pb, tid);
        }
        if (kt + 2 < nkt) {
            ldA4(g_sim, TT, rowA, (kt + 2) * BK, pa, tid);
            ldBk((kt + 2) * BK, colB, pb, tid);
        }
        mma_body(dsm + (kt & 1) * STAGE_WORDS, acc, wm, wn, lane);
        __syncthreads();
    }

#pragma unroll
    for (int i = 0; i < 4; i++) {
        int t = rowA + (wm * 4 + i) * 16 + gr;
#pragma unroll
        for (int j = 0; j < 2; j++) {
            int d = colB + (wn * 2 + j) * 8 + gc * 2;
            *(float2*)&g_g[(size_t)t * DD + d]       = make_float2(acc[i][j][0], acc[i][j][1]);
            *(float2*)&g_g[(size_t)(t + 8) * DD + d] = make_float2(acc[i][j][2], acc[i][j][3]);
        }
    }
}

// ---------------- kernel 5: cross = g h^T + fused causal max ---------------
__global__ void __launch_bounds__(256, 2) k_cross() {
    extern __shared__ unsigned dsm[];
    int tid = threadIdx.x, lane = tid & 31, warp = tid >> 5;
    int wm = warp >> 2, wn = warp & 3, gr = lane >> 2, gc = lane & 3;
    int ib, jb;
    triDecodeB(blockIdx.x, ib, jb);
    int rowA = ib * BM, rowB = jb * BN;

    float acc[4][2][4];
#pragma unroll
    for (int i = 0; i < 4; i++)
#pragma unroll
        for (int j = 0; j < 2; j++)
#pragma unroll
            for (int e = 0; e < 4; e++) acc[i][j][e] = 0.f;

    float4 pa[4], pb[2];
    ldA4(g_g, DD, rowA, 0, pa, tid);
    ldBn(g_h, DD, rowB, 0, pb, tid);
    stA4(dsm, pa, tid);
    stBn(dsm, pb, tid);
    ldA4(g_g, DD, rowA, BK, pa, tid);
    ldBn(g_h, DD, rowB, BK, pb, tid);
    __syncthreads();

    for (int kt = 0; kt < NKT_FULL; kt++) {
        if (kt + 1 < NKT_FULL) {
            unsigned* nxt = dsm + ((kt + 1) & 1) * STAGE_WORDS;
            stA4(nxt, pa, tid);
            stBn(nxt, pb, tid);
        }
        if (kt + 2 < NKT_FULL) {
            ldA4(g_g, DD, rowA, (kt + 2) * BK, pa, tid);
            ldBn(g_h, DD, rowB, (kt + 2) * BK, pb, tid);
        }
        mma_body(dsm + (kt & 1) * STAGE_WORDS, acc, wm, wn, lane);
        __syncthreads();
    }

    // epilogue: maxQ[t] = max_{s<=t}(hn2[s] - 2*cross[t,s]) (monotone sqrt skipped)
    float hn[2][2];
#pragma unroll
    for (int j = 0; j < 2; j++)
#pragma unroll
        for (int e = 0; e < 2; e++)
            hn[j][e] = g_hn2[rowB + (wn * 2 + j) * 8 + gc * 2 + e];

    float* red = (float*)dsm;   // safe: all MMA reads done (post-loop sync)
#pragma unroll
    for (int i = 0; i < 4; i++) {
        int rloc = (wm * 4 + i) * 16 + gr;
        int t0 = rowA + rloc;
        float m0 = -3.0e38f, m1 = -3.0e38f;
#pragma unroll
        for (int j = 0; j < 2; j++)
#pragma unroll
            for (int e = 0; e < 2; e++) {
                int s = rowB + (wn * 2 + j) * 8 + gc * 2 + e;
                float q0 = hn[j][e] - 2.0f * acc[i][j][e];
                float q1 = hn[j][e] - 2.0f * acc[i][j][2 + e];
                if (s <= t0)     m0 = fmaxf(m0, q0);
                if (s <= t0 + 8) m1 = fmaxf(m1, q1);
            }
#pragma unroll
        for (int o = 1; o < 4; o <<= 1) {
            m0 = fmaxf(m0, __shfl_xor_sync(0xffffffffu, m0, o));
            m1 = fmaxf(m1, __shfl_xor_sync(0xffffffffu, m1, o));
        }
        if (gc == 0) {
            red[rloc * 4 + wn]       = m0;
            red[(rloc + 8) * 4 + wn] = m1;
        }
    }
    __syncthreads();
    if (tid < 128) {
        float m = fmaxf(fmaxf(red[tid * 4], red[tid * 4 + 1]),
                        fmaxf(red[tid * 4 + 2], red[tid * 4 + 3]));
        if (m > -2.0e38f) atomicMaxF(&g_maxQ[rowA + tid], m);
    }
}

// ---------------- kernel 6: final elementwise ------------------------------
__global__ void k_final(const float* __restrict__ m_t, const float* __restrict__ c_t,
                        const float* __restrict__ d_t, const float* __restrict__ mu,
                        float* __restrict__ out) {
    __shared__ float sh[32];
    int t = blockIdx.x;
    const float* hr = g_h + (size_t)t * DD;
    const float* gr = g_g + (size_t)t * DD;
    float dd = 0.f, gn2 = 0.f;
    for (int i = threadIdx.x; i < DD; i += blockDim.x) {
        float hv = hr[i], gv = gr[i];
        float df = hv - gv;
        dd += df * df;
        gn2 += gv * gv;
    }
    dd = blockReduceSum(dd, sh);
    gn2 = blockReduceSum(gn2, sh);
    if (threadIdx.x == 0) {
        float dist = sqrtf(fmaxf(dd, 1e-24f));
        float dmax = sqrtf(fmaxf(gn2 + g_maxQ[t], 1e-24f));
        if (dmax < 1e-6f) dmax = 1.0f;
        float ratio = dist / (dmax + 1e-8f);
        float stab = 1.0f - 0.3f * c_t[t] + 0.2f * d_t[t];
        float xi = 1.0f - mu[0] * m_t[t];
        float v = ratio * stab * xi;
        out[t] = fminf(fmaxf(v, 0.0f), 1.0f);
    }
}

// ---------------- launch ----------------------------------------------------
extern "C" void kernel_launch(void* const* d_in, const int* in_sizes, int n_in,
                              void* d_out, int out_size) {
    const float* x   = (const float*)d_in[0];
    const float* m_t = (const float*)d_in[1];
    const float* c_t = (const float*)d_in[2];
    const float* d_t = (const float*)d_in[3];
    const float* mu  = (const float*)d_in[4];
    float* out = (float*)d_out;

    cudaFuncSetAttribute(k_sim,   cudaFuncAttributeMaxDynamicSharedMemorySize, DSMEM);
    cudaFuncSetAttribute(k_g,     cudaFuncAttributeMaxDynamicSharedMemorySize, DSMEM);
    cudaFuncSetAttribute(k_cross, cudaFuncAttributeMaxDynamicSharedMemorySize, DSMEM);

    k_normalize<<<TT, 256>>>(x);
    k_tables<<<TT / 256, 256>>>();
    k_sim<<<NPAIRB, 256, DSMEM>>>();
    k_softmax<<<TT, 256>>>();
    k_g<<<dim3(DD / BN, NROWB), 256, DSMEM>>>();
    k_cross<<<NPAIRB, 256, DSMEM>>>();
    k_final<<<TT, 256>>>(m_t, c_t, d_t, mu, out);
}